// round 10
// baseline (speedup 1.0000x reference)
#include <cuda_runtime.h>

// Fused Poincare-ball: y = proj(expmap0(relu(logmap0(x))))
// CONVERGED OPTIMUM (best of 9 rounds): 4 threads per row (D=64), 4 x float4
// per thread, 256-thread blocks, one CTA per 64 rows.
// Single pass: relu commutes with the positive logmap0 scale, so ||x|| and
// ||relu(x)|| come from one read; expmap0/proj norms are analytic.
// Pinned at the chip's mixed r/w HBM ceiling (~6.8 TB/s, invariant across
// occ 42-79%, MLP 4-8, block 256/512, one-shot/persistent). Traffic minimal.

#define MIN_NORM  1e-7f
#define BALL_EPS  4e-3f
#define ATANH_EPS 1e-7f

__global__ __launch_bounds__(256)
void act_hyp_kernel(const float4* __restrict__ x,
                    const float* __restrict__ c,
                    float4* __restrict__ out,
                    int nrows)
{
    const int t    = blockIdx.x * blockDim.x + threadIdx.x;
    const int row  = t >> 2;
    if (row >= nrows) return;
    const int lane = t & 3;

    const float4* xp = x + (size_t)row * 16 + lane;

    // Front-batch 4 x LDG.128 (64 B of this row per thread)
    float4 v[4];
    #pragma unroll
    for (int i = 0; i < 4; i++) v[i] = __ldcs(xp + i * 4);

    // relu'd copy + both squared sums in one pass
    float r[16];
    float s2  = 0.0f;
    float s2p = 0.0f;
    #pragma unroll
    for (int i = 0; i < 4; i++) {
        float a0 = v[i].x, a1 = v[i].y, a2 = v[i].z, a3 = v[i].w;
        s2 = fmaf(a0, a0, s2); s2 = fmaf(a1, a1, s2);
        s2 = fmaf(a2, a2, s2); s2 = fmaf(a3, a3, s2);
        float b0 = fmaxf(a0, 0.0f), b1 = fmaxf(a1, 0.0f);
        float b2 = fmaxf(a2, 0.0f), b3 = fmaxf(a3, 0.0f);
        s2p = fmaf(b0, b0, s2p); s2p = fmaf(b1, b1, s2p);
        s2p = fmaf(b2, b2, s2p); s2p = fmaf(b3, b3, s2p);
        r[i*4+0] = b0; r[i*4+1] = b1; r[i*4+2] = b2; r[i*4+3] = b3;
    }

    // 4-lane xor reduction (groups of 4 aligned within the warp)
    #pragma unroll
    for (int off = 2; off >= 1; off >>= 1) {
        s2  += __shfl_xor_sync(0xFFFFFFFFu, s2,  off);
        s2p += __shfl_xor_sync(0xFFFFFFFFu, s2p, off);
    }

    const float sqrt_c = sqrtf(c[0]);

    // logmap0 scale: f = atanh(min(sc*xn, 1-eps)) / (sc*xn)
    // atanh(a) = 0.5*log((1+a)/(1-a)) via fast log (safe here: no cancellation)
    float xn  = fmaxf(sqrtf(s2), MIN_NORM);
    float sxn = sqrt_c * xn;
    float arg = fminf(sxn, 1.0f - ATANH_EPS);
    float ath = 0.5f * __logf(__fdividef(1.0f + arg, 1.0f - arg));
    float f   = __fdividef(ath, sxn);

    // expmap0 scale: t = tanh(sc*un)/(sc*un), un = f*||relu(x)|| (clamped)
    float un  = fmaxf(f * sqrtf(s2p), MIN_NORM);
    float sun = sqrt_c * un;
    float tt  = __fdividef(tanhf(sun), sun);

    // proj: ||y|| = un * tt analytically (both factors > 0)
    float yn      = fmaxf(un * tt, MIN_NORM);
    float maxnorm = __fdividef(1.0f - BALL_EPS, sqrt_c);
    float ps      = (yn > maxnorm) ? __fdividef(maxnorm, yn) : 1.0f;

    const float m = f * tt * ps;

    float4* op = out + (size_t)row * 16 + lane;
    #pragma unroll
    for (int i = 0; i < 4; i++) {
        float4 o;
        o.x = r[i*4+0] * m;
        o.y = r[i*4+1] * m;
        o.z = r[i*4+2] * m;
        o.w = r[i*4+3] * m;
        __stcs(op + i * 4, o);
    }
}

extern "C" void kernel_launch(void* const* d_in, const int* in_sizes, int n_in,
                              void* d_out, int out_size)
{
    const float4* x = (const float4*)d_in[0];
    const float*  c = (const float*)d_in[1];
    float4* out = (float4*)d_out;

    int nrows  = in_sizes[0] / 64;
    int blocks = (nrows + 63) / 64;   // 64 rows per 256-thread block
    act_hyp_kernel<<<blocks, 256>>>(x, c, out, nrows);
}

// round 11
// speedup vs baseline: 1.0023x; 1.0023x over previous
#include <cuda_runtime.h>

// Fused Poincare-ball: y = proj(expmap0(relu(logmap0(x))))
// Converged memory pattern (best of 10 rounds): 4 threads per row (D=64),
// 4 x float4 per thread. This round: 128-thread blocks (finest untested CTA
// grain; may smooth near/far-L2-die imbalance). Body identical to the record
// kernel. Pinned at the mixed r/w HBM ceiling (~6.8 TB/s); traffic minimal.

#define MIN_NORM  1e-7f
#define BALL_EPS  4e-3f
#define ATANH_EPS 1e-7f

__global__ __launch_bounds__(128)
void act_hyp_kernel(const float4* __restrict__ x,
                    const float* __restrict__ c,
                    float4* __restrict__ out,
                    int nrows)
{
    const int t    = blockIdx.x * blockDim.x + threadIdx.x;
    const int row  = t >> 2;
    if (row >= nrows) return;
    const int lane = t & 3;

    const float4* xp = x + (size_t)row * 16 + lane;

    // Front-batch 4 x LDG.128 (64 B of this row per thread)
    float4 v[4];
    #pragma unroll
    for (int i = 0; i < 4; i++) v[i] = __ldcs(xp + i * 4);

    // relu'd copy + both squared sums in one pass
    float r[16];
    float s2  = 0.0f;
    float s2p = 0.0f;
    #pragma unroll
    for (int i = 0; i < 4; i++) {
        float a0 = v[i].x, a1 = v[i].y, a2 = v[i].z, a3 = v[i].w;
        s2 = fmaf(a0, a0, s2); s2 = fmaf(a1, a1, s2);
        s2 = fmaf(a2, a2, s2); s2 = fmaf(a3, a3, s2);
        float b0 = fmaxf(a0, 0.0f), b1 = fmaxf(a1, 0.0f);
        float b2 = fmaxf(a2, 0.0f), b3 = fmaxf(a3, 0.0f);
        s2p = fmaf(b0, b0, s2p); s2p = fmaf(b1, b1, s2p);
        s2p = fmaf(b2, b2, s2p); s2p = fmaf(b3, b3, s2p);
        r[i*4+0] = b0; r[i*4+1] = b1; r[i*4+2] = b2; r[i*4+3] = b3;
    }

    // 4-lane xor reduction (groups of 4 aligned within the warp)
    #pragma unroll
    for (int off = 2; off >= 1; off >>= 1) {
        s2  += __shfl_xor_sync(0xFFFFFFFFu, s2,  off);
        s2p += __shfl_xor_sync(0xFFFFFFFFu, s2p, off);
    }

    const float sqrt_c = sqrtf(c[0]);

    // logmap0 scale: f = atanh(min(sc*xn, 1-eps)) / (sc*xn)
    // atanh(a) = 0.5*log((1+a)/(1-a)) via fast log (safe here: no cancellation)
    float xn  = fmaxf(sqrtf(s2), MIN_NORM);
    float sxn = sqrt_c * xn;
    float arg = fminf(sxn, 1.0f - ATANH_EPS);
    float ath = 0.5f * __logf(__fdividef(1.0f + arg, 1.0f - arg));
    float f   = __fdividef(ath, sxn);

    // expmap0 scale: t = tanh(sc*un)/(sc*un), un = f*||relu(x)|| (clamped)
    float un  = fmaxf(f * sqrtf(s2p), MIN_NORM);
    float sun = sqrt_c * un;
    float tt  = __fdividef(tanhf(sun), sun);

    // proj: ||y|| = un * tt analytically (both factors > 0)
    float yn      = fmaxf(un * tt, MIN_NORM);
    float maxnorm = __fdividef(1.0f - BALL_EPS, sqrt_c);
    float ps      = (yn > maxnorm) ? __fdividef(maxnorm, yn) : 1.0f;

    const float m = f * tt * ps;

    float4* op = out + (size_t)row * 16 + lane;
    #pragma unroll
    for (int i = 0; i < 4; i++) {
        float4 o;
        o.x = r[i*4+0] * m;
        o.y = r[i*4+1] * m;
        o.z = r[i*4+2] * m;
        o.w = r[i*4+3] * m;
        __stcs(op + i * 4, o);
    }
}

extern "C" void kernel_launch(void* const* d_in, const int* in_sizes, int n_in,
                              void* d_out, int out_size)
{
    const float4* x = (const float4*)d_in[0];
    const float*  c = (const float*)d_in[1];
    float4* out = (float4*)d_out;

    int nrows  = in_sizes[0] / 64;
    int blocks = (nrows + 31) / 32;   // 32 rows per 128-thread block
    act_hyp_kernel<<<blocks, 128>>>(x, c, out, nrows);
}